// round 1
// baseline (speedup 1.0000x reference)
#include <cuda_runtime.h>
#include <cuda_bf16.h>
#include <math.h>

#define B_    64
#define S_    256
#define BS    16384       // B_*S_
#define M_    64
#define QD_   128
#define QAD_  256
#define VD_   128
#define FD_   128

// ---------------- scratch (device globals; no allocs allowed) ----------------
__device__ float g_w[BS * M_];        // softmax attention weights  (4 MB)
__device__ float g_e[BS * VD_];       // erase gate                 (8 MB)
__device__ float g_a[BS * VD_];       // add vector                 (8 MB)
__device__ float g_reads[BS * VD_];   // read vectors               (8 MB)
__device__ float g_h[BS * FD_];       // hidden layer               (8 MB)
__device__ float g_partial[2 * 64];   // per-block (bce_sum, mask_sum)

// ============================================================================
// K1: w = softmax(q_emb @ mem_key^T)   rows=BS, K=128, N=64
//   tile: 64 rows x 64 cols, 256 threads, thread computes 4x4
// ============================================================================
__global__ void w_kernel(const int* __restrict__ q_data,
                         const float* __restrict__ q_w,
                         const float* __restrict__ mem_key) {
    __shared__ float q_sh[64][33];
    __shared__ float k_sh[64][33];
    __shared__ float l_sh[64][65];
    __shared__ int   idx_sh[64];

    int tid = threadIdx.x;                 // 256
    int r0  = blockIdx.x * 64;
    if (tid < 64) idx_sh[tid] = q_data[r0 + tid];
    __syncthreads();

    int ty = tid >> 4, tx = tid & 15;
    float acc[4][4];
#pragma unroll
    for (int i = 0; i < 4; i++)
#pragma unroll
        for (int j = 0; j < 4; j++) acc[i][j] = 0.f;

    for (int kc = 0; kc < 4; kc++) {
        int k0 = kc * 32;
#pragma unroll
        for (int j = 0; j < 8; j++) {
            int i  = tid + 256 * j;
            int rr = i >> 5, kk = i & 31;
            q_sh[rr][kk] = q_w[(long)idx_sh[rr] * QD_ + k0 + kk];
            k_sh[rr][kk] = mem_key[rr * QD_ + k0 + kk];
        }
        __syncthreads();
#pragma unroll
        for (int kk = 0; kk < 32; kk++) {
            float qr[4], kr[4];
#pragma unroll
            for (int i = 0; i < 4; i++) qr[i] = q_sh[ty + 16 * i][kk];
#pragma unroll
            for (int j = 0; j < 4; j++) kr[j] = k_sh[tx + 16 * j][kk];
#pragma unroll
            for (int i = 0; i < 4; i++)
#pragma unroll
                for (int j = 0; j < 4; j++) acc[i][j] = fmaf(qr[i], kr[j], acc[i][j]);
        }
        __syncthreads();
    }

#pragma unroll
    for (int i = 0; i < 4; i++)
#pragma unroll
        for (int j = 0; j < 4; j++) l_sh[ty + 16 * i][tx + 16 * j] = acc[i][j];
    __syncthreads();

    // softmax over 64 cols: 8 warps, 8 rows each
    int wid = tid >> 5, lane = tid & 31;
    for (int rr = wid; rr < 64; rr += 8) {
        float v0 = l_sh[rr][lane], v1 = l_sh[rr][lane + 32];
        float mx = fmaxf(v0, v1);
#pragma unroll
        for (int o = 16; o; o >>= 1) mx = fmaxf(mx, __shfl_xor_sync(0xFFFFFFFFu, mx, o));
        float e0 = __expf(v0 - mx), e1 = __expf(v1 - mx);
        float s = e0 + e1;
#pragma unroll
        for (int o = 16; o; o >>= 1) s += __shfl_xor_sync(0xFFFFFFFFu, s, o);
        float inv = 1.f / s;
        g_w[(r0 + rr) * M_ + lane]      = e0 * inv;
        g_w[(r0 + rr) * M_ + 32 + lane] = e1 * inv;
    }
}

// ============================================================================
// K2: e = sigmoid(qa_emb @ erase_w^T + eb), a = tanh(qa_emb @ add_w^T + ab)
//   rows=BS, K=256, N=128; tile 64x32, 128 threads, 4x4 per thread, 2 matrices
// ============================================================================
__global__ void ea_kernel(const int* __restrict__ qa_data,
                          const float* __restrict__ qa_w,
                          const float* __restrict__ ew, const float* __restrict__ eb,
                          const float* __restrict__ aw, const float* __restrict__ ab) {
    __shared__ float qa_sh[64][33];
    __shared__ float we_sh[32][33];
    __shared__ float wa_sh[32][33];
    __shared__ int   idx_sh[64];

    int tid = threadIdx.x;                 // 128
    int rb = blockIdx.x >> 2, vb = blockIdx.x & 3;
    int r0 = rb * 64, v0 = vb * 32;
    if (tid < 64) idx_sh[tid] = qa_data[r0 + tid];
    __syncthreads();

    int ty = tid >> 3, tx = tid & 7;
    float acc_e[4][4], acc_a[4][4];
#pragma unroll
    for (int i = 0; i < 4; i++)
#pragma unroll
        for (int j = 0; j < 4; j++) { acc_e[i][j] = 0.f; acc_a[i][j] = 0.f; }

    for (int kc = 0; kc < 8; kc++) {
        int k0 = kc * 32;
#pragma unroll
        for (int j = 0; j < 16; j++) {
            int i  = tid + 128 * j;
            int rr = i >> 5, kk = i & 31;
            qa_sh[rr][kk] = qa_w[(long)idx_sh[rr] * QAD_ + k0 + kk];
        }
#pragma unroll
        for (int j = 0; j < 8; j++) {
            int i  = tid + 128 * j;
            int rr = i >> 5, kk = i & 31;
            we_sh[rr][kk] = ew[(v0 + rr) * QAD_ + k0 + kk];
            wa_sh[rr][kk] = aw[(v0 + rr) * QAD_ + k0 + kk];
        }
        __syncthreads();
#pragma unroll
        for (int kk = 0; kk < 32; kk++) {
            float qr[4], er[4], ar[4];
#pragma unroll
            for (int i = 0; i < 4; i++) qr[i] = qa_sh[ty + 16 * i][kk];
#pragma unroll
            for (int j = 0; j < 4; j++) { er[j] = we_sh[tx + 8 * j][kk]; ar[j] = wa_sh[tx + 8 * j][kk]; }
#pragma unroll
            for (int i = 0; i < 4; i++)
#pragma unroll
                for (int j = 0; j < 4; j++) {
                    acc_e[i][j] = fmaf(qr[i], er[j], acc_e[i][j]);
                    acc_a[i][j] = fmaf(qr[i], ar[j], acc_a[i][j]);
                }
        }
        __syncthreads();
    }

#pragma unroll
    for (int i = 0; i < 4; i++) {
        int r = r0 + ty + 16 * i;
#pragma unroll
        for (int j = 0; j < 4; j++) {
            int v = v0 + tx + 8 * j;
            float xe = acc_e[i][j] + eb[v];
            float xa = acc_a[i][j] + ab[v];
            g_e[r * VD_ + v] = 1.f / (1.f + __expf(-xe));
            g_a[r * VD_ + v] = tanhf(xa);
        }
    }
}

// ============================================================================
// K3: sequential memory scan.  block = (batch, v-half): 128 threads.
//   thread = (v within half, m-half): owns 32 mem values in registers.
// ============================================================================
__global__ void scan_kernel(const float* __restrict__ mem_value0) {
    __shared__ float w_sh[2][M_];
    int b = blockIdx.x >> 1, vh = blockIdx.x & 1;
    int tid = threadIdx.x;                 // 128
    int mh = tid & 1, vloc = tid >> 1;
    int v = vh * 64 + vloc;

    float mem[32];
#pragma unroll
    for (int i = 0; i < 32; i++) mem[i] = mem_value0[(mh * 32 + i) * VD_ + v];

    int rbase = b * S_;
    if (tid < 64) w_sh[0][tid] = g_w[rbase * M_ + tid];
    float e_c = g_e[rbase * VD_ + v];
    float a_c = g_a[rbase * VD_ + v];

    for (int t = 0; t < S_; t++) {
        __syncthreads();   // w_sh[t&1] ready; prev readers of w_sh[(t+1)&1] done
        float e_n = 0.f, a_n = 0.f;
        if (t + 1 < S_) {
            int rn = rbase + t + 1;
            if (tid < 64) w_sh[(t + 1) & 1][tid] = g_w[rn * M_ + tid];
            e_n = g_e[rn * VD_ + v];
            a_n = g_a[rn * VD_ + v];
        }
        const float* ws = w_sh[t & 1] + mh * 32;
        float rd = 0.f;
#pragma unroll
        for (int i = 0; i < 32; i++) {
            float wm = ws[i];
            float tt = fmaf(-e_c, mem[i], a_c);     // a - e*mem
            rd = fmaf(wm, mem[i], rd);              // read (old mem)
            mem[i] = fmaf(wm, tt, mem[i]);          // mem += w*(a - e*mem)
        }
        rd += __shfl_xor_sync(0xFFFFFFFFu, rd, 1);
        if (mh == 0) g_reads[(rbase + t) * VD_ + v] = rd;
        e_c = e_n; a_c = a_n;
    }
}

// ============================================================================
// K4: h = tanh([reads, q_emb] @ read_w^T + rb)   rows=BS, K=256, N=128
// ============================================================================
__global__ void read_kernel(const int* __restrict__ q_data,
                            const float* __restrict__ q_w,
                            const float* __restrict__ rw,
                            const float* __restrict__ rb) {
    __shared__ float f_sh[64][33];
    __shared__ float w_sh[32][33];
    __shared__ int   idx_sh[64];

    int tid = threadIdx.x;                 // 128
    int rbk = blockIdx.x >> 2, vb = blockIdx.x & 3;
    int r0 = rbk * 64, v0 = vb * 32;
    if (tid < 64) idx_sh[tid] = q_data[r0 + tid];
    __syncthreads();

    int ty = tid >> 3, tx = tid & 7;
    float acc[4][4];
#pragma unroll
    for (int i = 0; i < 4; i++)
#pragma unroll
        for (int j = 0; j < 4; j++) acc[i][j] = 0.f;

    for (int kc = 0; kc < 8; kc++) {
        int k0 = kc * 32;
#pragma unroll
        for (int j = 0; j < 16; j++) {
            int i  = tid + 128 * j;
            int rr = i >> 5, kk = i & 31;
            float val;
            if (k0 < 128) val = g_reads[(r0 + rr) * VD_ + k0 + kk];
            else          val = q_w[(long)idx_sh[rr] * QD_ + (k0 - 128) + kk];
            f_sh[rr][kk] = val;
        }
#pragma unroll
        for (int j = 0; j < 8; j++) {
            int i  = tid + 128 * j;
            int rr = i >> 5, kk = i & 31;
            w_sh[rr][kk] = rw[(v0 + rr) * (VD_ + FD_) + k0 + kk];
        }
        __syncthreads();
#pragma unroll
        for (int kk = 0; kk < 32; kk++) {
            float fr[4], wr[4];
#pragma unroll
            for (int i = 0; i < 4; i++) fr[i] = f_sh[ty + 16 * i][kk];
#pragma unroll
            for (int j = 0; j < 4; j++) wr[j] = w_sh[tx + 8 * j][kk];
#pragma unroll
            for (int i = 0; i < 4; i++)
#pragma unroll
                for (int j = 0; j < 4; j++) acc[i][j] = fmaf(fr[i], wr[j], acc[i][j]);
        }
        __syncthreads();
    }

#pragma unroll
    for (int i = 0; i < 4; i++) {
        int r = r0 + ty + 16 * i;
#pragma unroll
        for (int j = 0; j < 4; j++) {
            int v = v0 + tx + 8 * j;
            g_h[r * FD_ + v] = tanhf(acc[i][j] + rb[v]);
        }
    }
}

// ============================================================================
// K5: logits = h @ pred_w^T + pb; pred = sigmoid; bce partial sums.
//   64 blocks x 256 threads; one warp per row (32 rows per warp).
// ============================================================================
__global__ void pred_kernel(const float* __restrict__ target,
                            const float* __restrict__ pw,
                            const float* __restrict__ pb,
                            float* __restrict__ out) {
    int tid = threadIdx.x;
    int lane = tid & 31, wid = tid >> 5;
    int gw = blockIdx.x * 8 + wid;         // 512 warps total
    float4 pw4 = ((const float4*)pw)[lane];
    float pbv = pb[0];

    float s_bce = 0.f, s_m = 0.f;
    for (int r = gw; r < BS; r += 512) {
        float4 h4 = ((const float4*)(g_h + r * FD_))[lane];
        float p = h4.x * pw4.x + h4.y * pw4.y + h4.z * pw4.z + h4.w * pw4.w;
#pragma unroll
        for (int o = 16; o; o >>= 1) p += __shfl_xor_sync(0xFFFFFFFFu, p, o);
        float logit = p + pbv;
        if (lane == 0) {
            float pred = 1.f / (1.f + __expf(-logit));
            float tgt  = target[r];
            out[1 + r]      = pred;
            out[1 + BS + r] = tgt;
            float spa = log1pf(__expf(-fabsf(logit)));
            float sp_n = fmaxf(-logit, 0.f) + spa;   // softplus(-logit)
            float sp_p = fmaxf(logit, 0.f) + spa;    // softplus(logit)
            float msk = (tgt >= 0.f) ? 1.f : 0.f;
            s_bce += (tgt * sp_n + (1.f - tgt) * sp_p) * msk;
            s_m   += msk;
        }
    }

    __shared__ float sb[8], sm[8];
    if (lane == 0) { sb[wid] = s_bce; sm[wid] = s_m; }
    __syncthreads();
    if (tid == 0) {
        float tb = 0.f, tm = 0.f;
#pragma unroll
        for (int i = 0; i < 8; i++) { tb += sb[i]; tm += sm[i]; }
        g_partial[2 * blockIdx.x]     = tb;
        g_partial[2 * blockIdx.x + 1] = tm;
    }
}

// ============================================================================
// K6: final loss reduction
// ============================================================================
__global__ void loss_kernel(float* __restrict__ out) {
    if (threadIdx.x == 0) {
        float tb = 0.f, tm = 0.f;
        for (int i = 0; i < 64; i++) { tb += g_partial[2 * i]; tm += g_partial[2 * i + 1]; }
        out[0] = tb / fmaxf(tm, 1.f);
    }
}

// ============================================================================
extern "C" void kernel_launch(void* const* d_in, const int* in_sizes, int n_in,
                              void* d_out, int out_size) {
    const int*   q_data    = (const int*)d_in[0];
    const int*   qa_data   = (const int*)d_in[1];
    const float* target    = (const float*)d_in[2];
    const float* q_embed   = (const float*)d_in[3];
    const float* qa_embed  = (const float*)d_in[4];
    const float* mem_key   = (const float*)d_in[5];
    const float* mem_val0  = (const float*)d_in[6];
    const float* erase_w   = (const float*)d_in[7];
    const float* erase_b   = (const float*)d_in[8];
    const float* add_w     = (const float*)d_in[9];
    const float* add_b     = (const float*)d_in[10];
    const float* read_w    = (const float*)d_in[11];
    const float* read_b    = (const float*)d_in[12];
    const float* pred_w    = (const float*)d_in[13];
    const float* pred_b    = (const float*)d_in[14];
    float* out = (float*)d_out;

    w_kernel   <<<BS / 64, 256>>>(q_data, q_embed, mem_key);
    ea_kernel  <<<(BS / 64) * 4, 128>>>(qa_data, qa_embed, erase_w, erase_b, add_w, add_b);
    scan_kernel<<<B_ * 2, 128>>>(mem_val0);
    read_kernel<<<(BS / 64) * 4, 128>>>(q_data, q_embed, read_w, read_b);
    pred_kernel<<<64, 256>>>(target, pred_w, pred_b, out);
    loss_kernel<<<1, 32>>>(out);
}

// round 2
// speedup vs baseline: 1.7857x; 1.7857x over previous
#include <cuda_runtime.h>
#include <cuda_bf16.h>
#include <math.h>

#define B_    64
#define S_    256
#define BS    16384
#define M_    64
#define QD_   128
#define QAD_  256
#define VD_   128
#define FD_   128

typedef unsigned long long ull;

// ---------------- scratch ----------------
__device__ float g_w[BS * M_];
__device__ float g_e[BS * VD_];
__device__ float g_a[BS * VD_];
__device__ float g_reads[BS * VD_];
__device__ float g_h[BS * FD_];
__device__ float g_partial[2 * 64];

// ---------------- f32x2 helpers ----------------
__device__ __forceinline__ ull dup2(float x) {
    ull r; unsigned xi = __float_as_uint(x);
    asm("mov.b64 %0, {%1, %1};" : "=l"(r) : "r"(xi));
    return r;
}
__device__ __forceinline__ ull pack2(float lo, float hi) {
    ull r; unsigned a = __float_as_uint(lo), b = __float_as_uint(hi);
    asm("mov.b64 %0, {%1, %2};" : "=l"(r) : "r"(a), "r"(b));
    return r;
}
__device__ __forceinline__ void unpack2(ull v, float& lo, float& hi) {
    unsigned a, b;
    asm("mov.b64 {%0, %1}, %2;" : "=r"(a), "=r"(b) : "l"(v));
    lo = __uint_as_float(a); hi = __uint_as_float(b);
}
__device__ __forceinline__ void fma2(ull& d, ull a, ull b) {
    asm("fma.rn.f32x2 %0, %1, %2, %0;" : "+l"(d) : "l"(a), "l"(b));
}

// ============================================================================
// K1: w = softmax(q_emb @ mem_key^T)   M=BS, N=64, K=128
//   BM=128, BN=64, BK=16, 256 threads, 8x4 per thread (f32x2 packed)
// ============================================================================
__global__ __launch_bounds__(256) void w_kernel(const int* __restrict__ q_data,
                                                const float* __restrict__ q_w,
                                                const float* __restrict__ mem_key) {
    __shared__ union {
        struct {
            __align__(16) float As[2][16][132];
            __align__(16) float Bs[2][16][68];
        } g;
        float logits[128][65];
    } sm;
    __shared__ int idx_sh[128];

    int tid = threadIdx.x;
    int r0  = blockIdx.x * 128;
    if (tid < 128) idx_sh[tid] = q_data[r0 + tid];
    __syncthreads();

    int tx = tid & 15, ty = tid >> 4;
    int rowL = tid >> 2;            // 0..63
    int kq   = (tid & 3) * 4;

    ull acc[8][2];
#pragma unroll
    for (int i = 0; i < 8; i++) { acc[i][0] = 0ull; acc[i][1] = 0ull; }

    float4 pa0, pa1, pb0;
    // prologue: chunk 0
    pa0 = *(const float4*)(q_w + (long)idx_sh[rowL] * QD_ + kq);
    pa1 = *(const float4*)(q_w + (long)idx_sh[rowL + 64] * QD_ + kq);
    pb0 = *(const float4*)(mem_key + rowL * QD_ + kq);
    {
        float* a = &sm.g.As[0][kq][0];
        a[0*132 + rowL] = pa0.x; a[1*132 + rowL] = pa0.y; a[2*132 + rowL] = pa0.z; a[3*132 + rowL] = pa0.w;
        a[0*132 + rowL+64] = pa1.x; a[1*132 + rowL+64] = pa1.y; a[2*132 + rowL+64] = pa1.z; a[3*132 + rowL+64] = pa1.w;
        float* b = &sm.g.Bs[0][kq][0];
        b[0*68 + rowL] = pb0.x; b[1*68 + rowL] = pb0.y; b[2*68 + rowL] = pb0.z; b[3*68 + rowL] = pb0.w;
    }
    __syncthreads();

    for (int c = 0; c < 8; c++) {
        int cur = c & 1;
        if (c + 1 < 8) {
            int k0 = (c + 1) * 16;
            pa0 = *(const float4*)(q_w + (long)idx_sh[rowL] * QD_ + k0 + kq);
            pa1 = *(const float4*)(q_w + (long)idx_sh[rowL + 64] * QD_ + k0 + kq);
            pb0 = *(const float4*)(mem_key + rowL * QD_ + k0 + kq);
        }
#pragma unroll
        for (int kk = 0; kk < 16; kk++) {
            const float* ap = &sm.g.As[cur][kk][ty * 8];
            float4 a0 = *(const float4*)ap;
            float4 a1 = *(const float4*)(ap + 4);
            ulonglong2 bv = *(const ulonglong2*)&sm.g.Bs[cur][kk][tx * 4];
            ull ad[8] = {dup2(a0.x), dup2(a0.y), dup2(a0.z), dup2(a0.w),
                         dup2(a1.x), dup2(a1.y), dup2(a1.z), dup2(a1.w)};
#pragma unroll
            for (int i = 0; i < 8; i++) {
                fma2(acc[i][0], ad[i], bv.x);
                fma2(acc[i][1], ad[i], bv.y);
            }
        }
        if (c + 1 < 8) {
            int nb = (c + 1) & 1;
            float* a = &sm.g.As[nb][kq][0];
            a[0*132 + rowL] = pa0.x; a[1*132 + rowL] = pa0.y; a[2*132 + rowL] = pa0.z; a[3*132 + rowL] = pa0.w;
            a[0*132 + rowL+64] = pa1.x; a[1*132 + rowL+64] = pa1.y; a[2*132 + rowL+64] = pa1.z; a[3*132 + rowL+64] = pa1.w;
            float* b = &sm.g.Bs[nb][kq][0];
            b[0*68 + rowL] = pb0.x; b[1*68 + rowL] = pb0.y; b[2*68 + rowL] = pb0.z; b[3*68 + rowL] = pb0.w;
        }
        __syncthreads();
    }

    // write logits into smem (union reuse; gemm done, synced above)
#pragma unroll
    for (int i = 0; i < 8; i++) {
        float v0, v1, v2, v3;
        unpack2(acc[i][0], v0, v1);
        unpack2(acc[i][1], v2, v3);
        float* lr = &sm.logits[ty * 8 + i][tx * 4];
        lr[0] = v0; lr[1] = v1; lr[2] = v2; lr[3] = v3;
    }
    __syncthreads();

    int wid = tid >> 5, lane = tid & 31;
    for (int rr = wid; rr < 128; rr += 8) {
        float v0 = sm.logits[rr][lane], v1 = sm.logits[rr][lane + 32];
        float mx = fmaxf(v0, v1);
#pragma unroll
        for (int o = 16; o; o >>= 1) mx = fmaxf(mx, __shfl_xor_sync(0xFFFFFFFFu, mx, o));
        float e0 = __expf(v0 - mx), e1 = __expf(v1 - mx);
        float s = e0 + e1;
#pragma unroll
        for (int o = 16; o; o >>= 1) s += __shfl_xor_sync(0xFFFFFFFFu, s, o);
        float inv = 1.f / s;
        g_w[(r0 + rr) * M_ + lane]      = e0 * inv;
        g_w[(r0 + rr) * M_ + 32 + lane] = e1 * inv;
    }
}

// ============================================================================
// K2: stacked e/a GEMM.  M=BS, N=128 (per half), K=256.
//   BM=128, BN=128, BK=16, 256 threads, 8x8 per thread, grid.y = half (0:e,1:a)
// ============================================================================
__global__ __launch_bounds__(256) void ea_kernel(const int* __restrict__ qa_data,
                                                 const float* __restrict__ qa_w,
                                                 const float* __restrict__ ew, const float* __restrict__ eb,
                                                 const float* __restrict__ aw, const float* __restrict__ ab) {
    __shared__ __align__(16) float As[2][16][132];
    __shared__ __align__(16) float Bs[2][16][132];
    __shared__ int idx_sh[128];

    int tid = threadIdx.x;
    int r0  = blockIdx.x * 128;
    int half = blockIdx.y;
    const float* W    = half ? aw : ew;
    const float* bias = half ? ab : eb;
    if (tid < 128) idx_sh[tid] = qa_data[r0 + tid];
    __syncthreads();

    int tx = tid & 15, ty = tid >> 4;
    int rowL = tid >> 2;
    int kq   = (tid & 3) * 4;

    ull acc[8][4];
#pragma unroll
    for (int i = 0; i < 8; i++)
#pragma unroll
        for (int j = 0; j < 4; j++) acc[i][j] = 0ull;

    float4 pa0, pa1, pb0, pb1;
    pa0 = *(const float4*)(qa_w + (long)idx_sh[rowL] * QAD_ + kq);
    pa1 = *(const float4*)(qa_w + (long)idx_sh[rowL + 64] * QAD_ + kq);
    pb0 = *(const float4*)(W + rowL * QAD_ + kq);
    pb1 = *(const float4*)(W + (rowL + 64) * QAD_ + kq);
    {
        float* a = &As[0][kq][0];
        a[0*132+rowL]=pa0.x; a[1*132+rowL]=pa0.y; a[2*132+rowL]=pa0.z; a[3*132+rowL]=pa0.w;
        a[0*132+rowL+64]=pa1.x; a[1*132+rowL+64]=pa1.y; a[2*132+rowL+64]=pa1.z; a[3*132+rowL+64]=pa1.w;
        float* b = &Bs[0][kq][0];
        b[0*132+rowL]=pb0.x; b[1*132+rowL]=pb0.y; b[2*132+rowL]=pb0.z; b[3*132+rowL]=pb0.w;
        b[0*132+rowL+64]=pb1.x; b[1*132+rowL+64]=pb1.y; b[2*132+rowL+64]=pb1.z; b[3*132+rowL+64]=pb1.w;
    }
    __syncthreads();

    for (int c = 0; c < 16; c++) {
        int cur = c & 1;
        if (c + 1 < 16) {
            int k0 = (c + 1) * 16;
            pa0 = *(const float4*)(qa_w + (long)idx_sh[rowL] * QAD_ + k0 + kq);
            pa1 = *(const float4*)(qa_w + (long)idx_sh[rowL + 64] * QAD_ + k0 + kq);
            pb0 = *(const float4*)(W + rowL * QAD_ + k0 + kq);
            pb1 = *(const float4*)(W + (rowL + 64) * QAD_ + k0 + kq);
        }
#pragma unroll
        for (int kk = 0; kk < 16; kk++) {
            const float* ap = &As[cur][kk][ty * 8];
            float4 a0 = *(const float4*)ap;
            float4 a1 = *(const float4*)(ap + 4);
            ulonglong2 b01 = *(const ulonglong2*)&Bs[cur][kk][tx * 8];
            ulonglong2 b23 = *(const ulonglong2*)(&Bs[cur][kk][tx * 8] + 4);
            ull ad[8] = {dup2(a0.x), dup2(a0.y), dup2(a0.z), dup2(a0.w),
                         dup2(a1.x), dup2(a1.y), dup2(a1.z), dup2(a1.w)};
#pragma unroll
            for (int i = 0; i < 8; i++) {
                fma2(acc[i][0], ad[i], b01.x);
                fma2(acc[i][1], ad[i], b01.y);
                fma2(acc[i][2], ad[i], b23.x);
                fma2(acc[i][3], ad[i], b23.y);
            }
        }
        if (c + 1 < 16) {
            int nb = (c + 1) & 1;
            float* a = &As[nb][kq][0];
            a[0*132+rowL]=pa0.x; a[1*132+rowL]=pa0.y; a[2*132+rowL]=pa0.z; a[3*132+rowL]=pa0.w;
            a[0*132+rowL+64]=pa1.x; a[1*132+rowL+64]=pa1.y; a[2*132+rowL+64]=pa1.z; a[3*132+rowL+64]=pa1.w;
            float* b = &Bs[nb][kq][0];
            b[0*132+rowL]=pb0.x; b[1*132+rowL]=pb0.y; b[2*132+rowL]=pb0.z; b[3*132+rowL]=pb0.w;
            b[0*132+rowL+64]=pb1.x; b[1*132+rowL+64]=pb1.y; b[2*132+rowL+64]=pb1.z; b[3*132+rowL+64]=pb1.w;
        }
        __syncthreads();
    }

    float* dst = half ? g_a : g_e;
#pragma unroll
    for (int i = 0; i < 8; i++) {
        int r = r0 + ty * 8 + i;
        float o[8];
        unpack2(acc[i][0], o[0], o[1]);
        unpack2(acc[i][1], o[2], o[3]);
        unpack2(acc[i][2], o[4], o[5]);
        unpack2(acc[i][3], o[6], o[7]);
        float res[8];
#pragma unroll
        for (int j = 0; j < 8; j++) {
            int v = tx * 8 + j;
            float x = o[j] + bias[v];
            res[j] = half ? tanhf(x) : (1.f / (1.f + __expf(-x)));
        }
        float4* dp = (float4*)(dst + (long)r * VD_ + tx * 8);
        dp[0] = make_float4(res[0], res[1], res[2], res[3]);
        dp[1] = make_float4(res[4], res[5], res[6], res[7]);
    }
}

// ============================================================================
// K3: sequential memory scan.  128 blocks (batch x v-half), 256 threads.
//   All w/e/a for the block preloaded into 192KB dynamic smem.
// ============================================================================
__global__ __launch_bounds__(256) void scan_kernel(const float* __restrict__ mem_value0) {
    extern __shared__ float smd[];
    float* w_all = smd;                 // [S_][64]
    float* e_all = smd + S_ * 64;       // [S_][64]
    float* a_all = e_all + S_ * 64;     // [S_][64]

    int bb = blockIdx.x >> 1, vh = blockIdx.x & 1;
    int tid = threadIdx.x;
    int rbase = bb * S_;

    // preload w (contiguous 64KB)
    const float4* wsrc = (const float4*)(g_w + (long)rbase * M_);
    float4* wdst = (float4*)w_all;
    for (int i = tid; i < S_ * M_ / 4; i += 256) wdst[i] = wsrc[i];
    // preload e,a (strided rows)
    for (int f = tid; f < S_ * 16; f += 256) {
        int t = f >> 4, c = (f & 15) * 4;
        *(float4*)&e_all[t * 64 + c] = *(const float4*)(g_e + (long)(rbase + t) * VD_ + vh * 64 + c);
        *(float4*)&a_all[t * 64 + c] = *(const float4*)(g_a + (long)(rbase + t) * VD_ + vh * 64 + c);
    }
    __syncthreads();

    int lane = tid & 31, wid = tid >> 5;
    int mh = lane & 3, vl = lane >> 2;
    int vloc = wid * 8 + vl;            // 0..63
    int v = vh * 64 + vloc;
    int mbase = mh * 16;

    ull mm[8];
#pragma unroll
    for (int i = 0; i < 8; i++) {
        int m0 = mbase + 2 * i;
        mm[i] = pack2(mem_value0[m0 * VD_ + v], mem_value0[(m0 + 1) * VD_ + v]);
    }

    for (int t = 0; t < S_; t++) {
        float ec = e_all[t * 64 + vloc];
        float ac = a_all[t * 64 + vloc];
        ull ne2 = dup2(-ec);
        ull a2v = dup2(ac);
        const ull* wp = (const ull*)&w_all[t * 64 + mbase];
        ull rd2 = 0ull;
#pragma unroll
        for (int i = 0; i < 8; i++) {
            ull w2 = wp[i];
            ull tt = a2v; fma2(tt, ne2, mm[i]);   // a - e*mem
            fma2(rd2, w2, mm[i]);                 // read uses old mem
            fma2(mm[i], w2, tt);                  // mem += w*(a - e*mem)
        }
        float rl, rh; unpack2(rd2, rl, rh);
        float rd = rl + rh;
        rd += __shfl_xor_sync(0xFFFFFFFFu, rd, 1);
        rd += __shfl_xor_sync(0xFFFFFFFFu, rd, 2);
        if (mh == 0) g_reads[(long)(rbase + t) * VD_ + v] = rd;
    }
}

// ============================================================================
// K4: h = tanh([reads, q_emb] @ read_w^T + rb)  M=BS, N=128, K=256
// ============================================================================
__global__ __launch_bounds__(256) void read_kernel(const int* __restrict__ q_data,
                                                   const float* __restrict__ q_w,
                                                   const float* __restrict__ rw,
                                                   const float* __restrict__ rb) {
    __shared__ __align__(16) float As[2][16][132];
    __shared__ __align__(16) float Bs[2][16][132];
    __shared__ int idx_sh[128];

    int tid = threadIdx.x;
    int r0  = blockIdx.x * 128;
    if (tid < 128) idx_sh[tid] = q_data[r0 + tid];
    __syncthreads();

    int tx = tid & 15, ty = tid >> 4;
    int rowL = tid >> 2;
    int kq   = (tid & 3) * 4;

    ull acc[8][4];
#pragma unroll
    for (int i = 0; i < 8; i++)
#pragma unroll
        for (int j = 0; j < 4; j++) acc[i][j] = 0ull;

    float4 pa0, pa1, pb0, pb1;
    // chunk 0 (k0=0 < 128 -> reads)
    pa0 = *(const float4*)(g_reads + (long)(r0 + rowL) * VD_ + kq);
    pa1 = *(const float4*)(g_reads + (long)(r0 + rowL + 64) * VD_ + kq);
    pb0 = *(const float4*)(rw + rowL * 256 + kq);
    pb1 = *(const float4*)(rw + (rowL + 64) * 256 + kq);
    {
        float* a = &As[0][kq][0];
        a[0*132+rowL]=pa0.x; a[1*132+rowL]=pa0.y; a[2*132+rowL]=pa0.z; a[3*132+rowL]=pa0.w;
        a[0*132+rowL+64]=pa1.x; a[1*132+rowL+64]=pa1.y; a[2*132+rowL+64]=pa1.z; a[3*132+rowL+64]=pa1.w;
        float* b = &Bs[0][kq][0];
        b[0*132+rowL]=pb0.x; b[1*132+rowL]=pb0.y; b[2*132+rowL]=pb0.z; b[3*132+rowL]=pb0.w;
        b[0*132+rowL+64]=pb1.x; b[1*132+rowL+64]=pb1.y; b[2*132+rowL+64]=pb1.z; b[3*132+rowL+64]=pb1.w;
    }
    __syncthreads();

    for (int c = 0; c < 16; c++) {
        int cur = c & 1;
        if (c + 1 < 16) {
            int k0 = (c + 1) * 16;
            if (k0 < 128) {
                pa0 = *(const float4*)(g_reads + (long)(r0 + rowL) * VD_ + k0 + kq);
                pa1 = *(const float4*)(g_reads + (long)(r0 + rowL + 64) * VD_ + k0 + kq);
            } else {
                pa0 = *(const float4*)(q_w + (long)idx_sh[rowL] * QD_ + (k0 - 128) + kq);
                pa1 = *(const float4*)(q_w + (long)idx_sh[rowL + 64] * QD_ + (k0 - 128) + kq);
            }
            pb0 = *(const float4*)(rw + rowL * 256 + k0 + kq);
            pb1 = *(const float4*)(rw + (rowL + 64) * 256 + k0 + kq);
        }
#pragma unroll
        for (int kk = 0; kk < 16; kk++) {
            const float* ap = &As[cur][kk][ty * 8];
            float4 a0 = *(const float4*)ap;
            float4 a1 = *(const float4*)(ap + 4);
            ulonglong2 b01 = *(const ulonglong2*)&Bs[cur][kk][tx * 8];
            ulonglong2 b23 = *(const ulonglong2*)(&Bs[cur][kk][tx * 8] + 4);
            ull ad[8] = {dup2(a0.x), dup2(a0.y), dup2(a0.z), dup2(a0.w),
                         dup2(a1.x), dup2(a1.y), dup2(a1.z), dup2(a1.w)};
#pragma unroll
            for (int i = 0; i < 8; i++) {
                fma2(acc[i][0], ad[i], b01.x);
                fma2(acc[i][1], ad[i], b01.y);
                fma2(acc[i][2], ad[i], b23.x);
                fma2(acc[i][3], ad[i], b23.y);
            }
        }
        if (c + 1 < 16) {
            int nb = (c + 1) & 1;
            float* a = &As[nb][kq][0];
            a[0*132+rowL]=pa0.x; a[1*132+rowL]=pa0.y; a[2*132+rowL]=pa0.z; a[3*132+rowL]=pa0.w;
            a[0*132+rowL+64]=pa1.x; a[1*132+rowL+64]=pa1.y; a[2*132+rowL+64]=pa1.z; a[3*132+rowL+64]=pa1.w;
            float* b = &Bs[nb][kq][0];
            b[0*132+rowL]=pb0.x; b[1*132+rowL]=pb0.y; b[2*132+rowL]=pb0.z; b[3*132+rowL]=pb0.w;
            b[0*132+rowL+64]=pb1.x; b[1*132+rowL+64]=pb1.y; b[2*132+rowL+64]=pb1.z; b[3*132+rowL+64]=pb1.w;
        }
        __syncthreads();
    }

#pragma unroll
    for (int i = 0; i < 8; i++) {
        int r = r0 + ty * 8 + i;
        float o[8];
        unpack2(acc[i][0], o[0], o[1]);
        unpack2(acc[i][1], o[2], o[3]);
        unpack2(acc[i][2], o[4], o[5]);
        unpack2(acc[i][3], o[6], o[7]);
        float res[8];
#pragma unroll
        for (int j = 0; j < 8; j++) {
            int vv = tx * 8 + j;
            res[j] = tanhf(o[j] + rb[vv]);
        }
        float4* dp = (float4*)(g_h + (long)r * FD_ + tx * 8);
        dp[0] = make_float4(res[0], res[1], res[2], res[3]);
        dp[1] = make_float4(res[4], res[5], res[6], res[7]);
    }
}

// ============================================================================
// K5: logits / sigmoid / bce partials
// ============================================================================
__global__ void pred_kernel(const float* __restrict__ target,
                            const float* __restrict__ pw,
                            const float* __restrict__ pb,
                            float* __restrict__ out) {
    int tid = threadIdx.x;
    int lane = tid & 31, wid = tid >> 5;
    int gw = blockIdx.x * 8 + wid;
    float4 pw4 = ((const float4*)pw)[lane];
    float pbv = pb[0];

    float s_bce = 0.f, s_m = 0.f;
    for (int r = gw; r < BS; r += 512) {
        float4 h4 = ((const float4*)(g_h + (long)r * FD_))[lane];
        float p = h4.x * pw4.x + h4.y * pw4.y + h4.z * pw4.z + h4.w * pw4.w;
#pragma unroll
        for (int o = 16; o; o >>= 1) p += __shfl_xor_sync(0xFFFFFFFFu, p, o);
        float logit = p + pbv;
        if (lane == 0) {
            float pred = 1.f / (1.f + __expf(-logit));
            float tgt  = target[r];
            out[1 + r]      = pred;
            out[1 + BS + r] = tgt;
            float spa = log1pf(__expf(-fabsf(logit)));
            float sp_n = fmaxf(-logit, 0.f) + spa;
            float sp_p = fmaxf(logit, 0.f) + spa;
            float msk = (tgt >= 0.f) ? 1.f : 0.f;
            s_bce += (tgt * sp_n + (1.f - tgt) * sp_p) * msk;
            s_m   += msk;
        }
    }

    __shared__ float sb[8], smm[8];
    if (lane == 0) { sb[wid] = s_bce; smm[wid] = s_m; }
    __syncthreads();
    if (tid == 0) {
        float tb = 0.f, tm = 0.f;
#pragma unroll
        for (int i = 0; i < 8; i++) { tb += sb[i]; tm += smm[i]; }
        g_partial[2 * blockIdx.x]     = tb;
        g_partial[2 * blockIdx.x + 1] = tm;
    }
}

__global__ void loss_kernel(float* __restrict__ out) {
    if (threadIdx.x == 0) {
        float tb = 0.f, tm = 0.f;
        for (int i = 0; i < 64; i++) { tb += g_partial[2 * i]; tm += g_partial[2 * i + 1]; }
        out[0] = tb / fmaxf(tm, 1.f);
    }
}

// ============================================================================
extern "C" void kernel_launch(void* const* d_in, const int* in_sizes, int n_in,
                              void* d_out, int out_size) {
    const int*   q_data    = (const int*)d_in[0];
    const int*   qa_data   = (const int*)d_in[1];
    const float* target    = (const float*)d_in[2];
    const float* q_embed   = (const float*)d_in[3];
    const float* qa_embed  = (const float*)d_in[4];
    const float* mem_key   = (const float*)d_in[5];
    const float* mem_val0  = (const float*)d_in[6];
    const float* erase_w   = (const float*)d_in[7];
    const float* erase_b   = (const float*)d_in[8];
    const float* add_w     = (const float*)d_in[9];
    const float* add_b     = (const float*)d_in[10];
    const float* read_w    = (const float*)d_in[11];
    const float* read_b    = (const float*)d_in[12];
    const float* pred_w    = (const float*)d_in[13];
    const float* pred_b    = (const float*)d_in[14];
    float* out = (float*)d_out;

    static bool attr_done = false;
    if (!attr_done) {
        cudaFuncSetAttribute(scan_kernel, cudaFuncAttributeMaxDynamicSharedMemorySize, 196608);
        attr_done = true;
    }

    w_kernel   <<<BS / 128, 256>>>(q_data, q_embed, mem_key);
    ea_kernel  <<<dim3(BS / 128, 2), 256>>>(qa_data, qa_embed, erase_w, erase_b, add_w, add_b);
    scan_kernel<<<B_ * 2, 256, 196608>>>(mem_val0);
    read_kernel<<<BS / 128, 256>>>(q_data, q_embed, read_w, read_b);
    pred_kernel<<<64, 256>>>(target, pred_w, pred_b, out);
    loss_kernel<<<1, 32>>>(out);
}